// round 14
// baseline (speedup 1.0000x reference)
#include <cuda_runtime.h>
#include <cuda_fp16.h>
#include <cstdint>

#define S_LEN 2048
#define EMB   1024
#define NH    16
#define HD    64
#define BATCH 2
#define MTOT  (BATCH*S_LEN)   // 4096

// Scratch (device globals: allocation-free)
__device__ __half g_xh [MTOT*EMB];            // x in fp16
__device__ __half g_wqh[EMB*EMB];
__device__ __half g_wkh[EMB*EMB];
__device__ __half g_wvh[EMB*EMB];
__device__ __half g_woh[EMB*EMB];
__device__ __half g_q[BATCH*NH*S_LEN*HD];     // Q pre-scaled by 1/8
__device__ __half g_k[BATCH*NH*S_LEN*HD];
__device__ __half g_v[BATCH*NH*S_LEN*HD];
__device__ __half g_attnh[MTOT*EMB];          // attention output, fp16

#define SSTRIDE 72                   // smem row stride in halves (144 B)
#define TILE_A2 (64*SSTRIDE*2)       // 9216 B  (64-row A tile)
#define TILE_B2 (128*SSTRIDE*2)      // 18432 B (128-row B tile)
#define STG_G2  (TILE_A2 + TILE_B2)  // 27648 B per stage
#define TILE_Q  (128*SSTRIDE*2)      // 18432 B
#define TILE_KV (64*SSTRIDE*2)       // 9216 B
#define STG_KV  (2*TILE_KV)          // 18432 B per stage (K + V)

// ---------------------------------------------------------------------------
// helpers
// ---------------------------------------------------------------------------
__device__ __forceinline__ uint32_t smem_u32(const void* p) {
    uint32_t a;
    asm("{ .reg .u64 t; cvta.to.shared.u64 t, %1; cvt.u32.u64 %0, t; }" : "=r"(a) : "l"(p));
    return a;
}
__device__ __forceinline__ uint32_t h2u(float a, float b) {
    __half2 h = __floats2half2_rn(a, b);
    return *(uint32_t*)&h;
}
__device__ __forceinline__ void cp16(uint32_t dst, const void* src) {
    asm volatile("cp.async.cg.shared.global [%0], [%1], 16;" :: "r"(dst), "l"(src));
}
#define CP_COMMIT() asm volatile("cp.async.commit_group;" ::: "memory")
#define CP_WAIT1()  asm volatile("cp.async.wait_group 1;" ::: "memory")
#define CP_WAIT0()  asm volatile("cp.async.wait_group 0;" ::: "memory")

__device__ __forceinline__ void ldsm4(uint32_t* r, uint32_t a) {
    asm volatile("ldmatrix.sync.aligned.m8n8.x4.shared.b16 {%0,%1,%2,%3}, [%4];"
        : "=r"(r[0]), "=r"(r[1]), "=r"(r[2]), "=r"(r[3]) : "r"(a));
}
__device__ __forceinline__ void ldsm4t(uint32_t* r, uint32_t a) {
    asm volatile("ldmatrix.sync.aligned.m8n8.x4.trans.shared.b16 {%0,%1,%2,%3}, [%4];"
        : "=r"(r[0]), "=r"(r[1]), "=r"(r[2]), "=r"(r[3]) : "r"(a));
}
__device__ __forceinline__ void mma16816(float* d, const uint32_t* a, uint32_t b0, uint32_t b1) {
    asm volatile(
        "mma.sync.aligned.m16n8k16.row.col.f32.f16.f16.f32 "
        "{%0,%1,%2,%3}, {%4,%5,%6,%7}, {%8,%9}, {%0,%1,%2,%3};"
        : "+f"(d[0]), "+f"(d[1]), "+f"(d[2]), "+f"(d[3])
        : "r"(a[0]), "r"(a[1]), "r"(a[2]), "r"(a[3]), "r"(b0), "r"(b1));
}

// ---------------------------------------------------------------------------
// fp32 -> fp16 pre-convert
// ---------------------------------------------------------------------------
#define XG  (MTOT*EMB/8)      // 524288
#define WG  (EMB*EMB/8)       // 131072

__global__ __launch_bounds__(256)
void cvt_kernel(const float* __restrict__ x,  const float* __restrict__ wq,
                const float* __restrict__ wk, const float* __restrict__ wv,
                const float* __restrict__ wo)
{
    int g = blockIdx.x * 256 + threadIdx.x;
    const float* src; __half* dst; int off;
    if (g < XG)             { src = x;  dst = g_xh;  off = g; }
    else if (g < XG + WG)   { src = wq; dst = g_wqh; off = g - XG; }
    else if (g < XG + 2*WG) { src = wk; dst = g_wkh; off = g - XG - WG; }
    else if (g < XG + 3*WG) { src = wv; dst = g_wvh; off = g - XG - 2*WG; }
    else                    { src = wo; dst = g_woh; off = g - XG - 3*WG; }
    float4 f0 = *(const float4*)(src + (size_t)off * 8);
    float4 f1 = *(const float4*)(src + (size_t)off * 8 + 4);
    uint4 o;
    o.x = h2u(f0.x, f0.y); o.y = h2u(f0.z, f0.w);
    o.z = h2u(f1.x, f1.y); o.w = h2u(f1.z, f1.w);
    *(uint4*)(dst + (size_t)off * 8) = o;
}

// ---------------------------------------------------------------------------
// HGEMM: CTA tile 64x128, 8 warps (2m x 4n), warp tile 32x32.
// 3-stage cp.async pipeline (prefetch distance 2 — loads get ~2 chunk-times
// to land), ONE barrier per chunk, 82.9 KB smem -> 2 CTAs/SM.
// MODE 0: fp32 C.  MODE 1: fp16 scatter with scale.
// ---------------------------------------------------------------------------
template <int MODE>
__device__ __forceinline__
void hgemm_body(const __half* __restrict__ A, const __half* __restrict__ W,
                const float* __restrict__ bias, void* __restrict__ Cout, float oscale)
{
    extern __shared__ char smraw[];
    const uint32_t sbase = smem_u32(smraw);

    const int tid = threadIdx.x;
    const int wid = tid >> 5, lane = tid & 31;
    const int wm = wid >> 2, wn = wid & 3;        // 2 x 4 warp grid
    const int m0 = blockIdx.y * 64, n0 = blockIdx.x * 128;

    float acc[2][4][4];
    #pragma unroll
    for (int mt = 0; mt < 2; mt++)
        #pragma unroll
        for (int nt = 0; nt < 4; nt++)
            #pragma unroll
            for (int r = 0; r < 4; r++) acc[mt][nt][r] = 0.0f;

    const __half* Ag = A + (size_t)m0 * EMB;
    const __half* Bg = W + (size_t)n0 * EMB;

    const int arow = tid >> 2;             // 0..63
    const int au0  = (tid & 3) << 1;       // 0,2,4,6
    const int brow = tid >> 1;             // 0..127
    const int bu0  = (tid & 1) << 2;       // 0,4

    auto prefetch = [&](int chunk, int s) {
        const int k1 = chunk * 64;
        const uint32_t sa = sbase + s * STG_G2;
        const uint32_t sb = sa + TILE_A2;
        #pragma unroll
        for (int u = 0; u < 2; u++)
            cp16(sa + arow * 144 + (au0 + u) * 16, Ag + (size_t)arow * EMB + k1 + (au0 + u) * 8);
        #pragma unroll
        for (int u = 0; u < 4; u++)
            cp16(sb + brow * 144 + (bu0 + u) * 16, Bg + (size_t)brow * EMB + k1 + (bu0 + u) * 8);
        CP_COMMIT();
    };

    const uint32_t aoff0 = (uint32_t)((wm * 32 +      (lane & 15)) * SSTRIDE + ((lane >> 4) << 3)) * 2;
    const uint32_t aoff1 = (uint32_t)((wm * 32 + 16 + (lane & 15)) * SSTRIDE + ((lane >> 4) << 3)) * 2;
    const int  brow0 = wn * 32 + ((lane >> 4) << 3) + (lane & 7);
    const uint32_t boffK = (uint32_t)(((lane >> 3) & 1) << 3) * 2;

    prefetch(0, 0);
    prefetch(1, 1);

    for (int kc = 0; kc < 16; kc++) {
        if (kc < 15) { CP_WAIT1(); } else { CP_WAIT0(); }
        __syncthreads();
        if (kc + 2 < 16) prefetch(kc + 2, (kc + 2) % 3);

        const uint32_t stA = sbase + (kc % 3) * STG_G2;
        const uint32_t stB = stA + TILE_A2;

        #pragma unroll
        for (int ks = 0; ks < 4; ks++) {
            uint32_t af[2][4], bf[2][4];
            ldsm4(af[0], stA + aoff0 + (uint32_t)(ks * 16) * 2);
            ldsm4(af[1], stA + aoff1 + (uint32_t)(ks * 16) * 2);
            #pragma unroll
            for (int nb = 0; nb < 2; nb++)
                ldsm4(bf[nb], stB + (uint32_t)((brow0 + nb * 16) * SSTRIDE + ks * 16) * 2 + boffK);
            #pragma unroll
            for (int mt = 0; mt < 2; mt++)
                #pragma unroll
                for (int nb = 0; nb < 2; nb++) {
                    mma16816(acc[mt][2 * nb],     af[mt], bf[nb][0], bf[nb][1]);
                    mma16816(acc[mt][2 * nb + 1], af[mt], bf[nb][2], bf[nb][3]);
                }
        }
    }

    #pragma unroll
    for (int mt = 0; mt < 2; mt++) {
        int rA = m0 + wm * 32 + mt * 16 + (lane >> 2);
        #pragma unroll
        for (int nt = 0; nt < 4; nt++) {
            int n = n0 + wn * 32 + nt * 8 + ((lane & 3) << 1);
            float b0 = bias[n], b1 = bias[n + 1];
            float v00 = acc[mt][nt][0] + b0, v01 = acc[mt][nt][1] + b1;
            float v10 = acc[mt][nt][2] + b0, v11 = acc[mt][nt][3] + b1;
            if (MODE == 0) {
                float* C = (float*)Cout;
                C[(size_t)rA * EMB + n]           = v00;
                C[(size_t)rA * EMB + n + 1]       = v01;
                C[(size_t)(rA + 8) * EMB + n]     = v10;
                C[(size_t)(rA + 8) * EMB + n + 1] = v11;
            } else {
                __half* C = (__half*)Cout;
                int h_ = n >> 6, d_ = n & 63;
                {
                    int b_ = rA >> 11, s_ = rA & 2047;
                    size_t base = (((size_t)(b_ * NH + h_) * S_LEN) + s_) * HD + d_;
                    *(__half2*)&C[base] = __floats2half2_rn(v00 * oscale, v01 * oscale);
                }
                {
                    int r2 = rA + 8;
                    int b_ = r2 >> 11, s_ = r2 & 2047;
                    size_t base = (((size_t)(b_ * NH + h_) * S_LEN) + s_) * HD + d_;
                    *(__half2*)&C[base] = __floats2half2_rn(v10 * oscale, v11 * oscale);
                }
            }
        }
    }
}

__global__ __launch_bounds__(256, 2)
void qkv_gemm_kernel(const float* __restrict__ bq, const float* __restrict__ bk,
                     const float* __restrict__ bv)
{
    if (blockIdx.z == 0)      hgemm_body<1>(g_xh, g_wqh, bq, g_q, 0.125f);
    else if (blockIdx.z == 1) hgemm_body<1>(g_xh, g_wkh, bk, g_k, 1.0f);
    else                      hgemm_body<1>(g_xh, g_wvh, bv, g_v, 1.0f);
}

__global__ __launch_bounds__(256, 2)
void out_gemm_kernel(const float* __restrict__ bo, float* __restrict__ out)
{
    hgemm_body<0>(g_attnh, g_woh, bo, out, 1.0f);
}

// ---------------------------------------------------------------------------
// Flash attention: unchanged (3-stage cp.async + frag double buffer).
// ---------------------------------------------------------------------------
__global__ __launch_bounds__(256, 2)
void flash_kernel()
{
    extern __shared__ char smraw[];
    const uint32_t sbase = smem_u32(smraw);
    const uint32_t Qu = sbase;
    const uint32_t kvbase = sbase + TILE_Q;

    const int tid = threadIdx.x, wid = tid >> 5, lane = tid & 31;
    const int qt = blockIdx.x;
    const int bh = blockIdx.y;

    const __half* Qg = g_q + ((size_t)bh * S_LEN + qt * 128) * HD;
    const __half* Kg = g_k + (size_t)bh * S_LEN * HD;
    const __half* Vg = g_v + (size_t)bh * S_LEN * HD;

    const int crow = tid >> 2;
    const int cu0  = (tid & 3) << 1;

    auto prefetch_kv = [&](int kt, int s) {
        const __half* Kp = Kg + (size_t)kt * 64 * HD;
        const __half* Vp = Vg + (size_t)kt * 64 * HD;
        const uint32_t ku = kvbase + s * STG_KV;
        const uint32_t vu = ku + TILE_KV;
        #pragma unroll
        for (int u = 0; u < 2; u++) {
            cp16(ku + crow * 144 + (cu0 + u) * 16, Kp + (size_t)crow * HD + (cu0 + u) * 8);
            cp16(vu + crow * 144 + (cu0 + u) * 16, Vp + (size_t)crow * HD + (cu0 + u) * 8);
        }
        CP_COMMIT();
    };

    // prologue
    {
        const int qrow = tid >> 1;
        const int qu0 = (tid & 1) << 2;
        #pragma unroll
        for (int u = 0; u < 4; u++)
            cp16(Qu + qrow * 144 + (qu0 + u) * 16, Qg + (size_t)qrow * HD + (qu0 + u) * 8);
        const uint32_t ku = kvbase, vu = kvbase + TILE_KV;
        #pragma unroll
        for (int u = 0; u < 2; u++) {
            cp16(ku + crow * 144 + (cu0 + u) * 16, Kg + (size_t)crow * HD + (cu0 + u) * 8);
            cp16(vu + crow * 144 + (cu0 + u) * 16, Vg + (size_t)crow * HD + (cu0 + u) * 8);
        }
        CP_COMMIT();
    }
    prefetch_kv(1, 1);

    float accO[8][4];
    #pragma unroll
    for (int dt = 0; dt < 8; dt++)
        #pragma unroll
        for (int r = 0; r < 4; r++) accO[dt][r] = 0.0f;
    float mA = -1e30f, mB = -1e30f, lA = 0.0f, lB = 0.0f;

    const int mrow = wid * 16;
    const uint32_t qoff = (uint32_t)((mrow + (lane & 15)) * SSTRIDE + ((lane >> 4) << 3)) * 2;
    const int  krow0 = ((lane >> 4) << 3) + (lane & 7);
    const uint32_t koffK = (uint32_t)(((lane >> 3) & 1) << 3) * 2;
    const int  vrow0 = (((lane >> 3) & 1) << 3) + (lane & 7);
    const uint32_t vcol0 = (uint32_t)((lane >> 4) << 3) * 2;

    for (int kt = 0; kt < S_LEN / 64; kt++) {
        if (kt < S_LEN / 64 - 1) { CP_WAIT1(); } else { CP_WAIT0(); }
        __syncthreads();
        if (kt + 2 < S_LEN / 64) prefetch_kv(kt + 2, (kt + 2) % 3);

        const uint32_t Ku = kvbase + (kt % 3) * STG_KV;
        const uint32_t Vu = Ku + TILE_KV;

        float sacc[8][4];
        #pragma unroll
        for (int nt = 0; nt < 8; nt++)
            #pragma unroll
            for (int r = 0; r < 4; r++) sacc[nt][r] = 0.0f;

        uint32_t qaf[2][4], kbf[2][4];
        ldsm4(qaf[0], Qu + qoff);
        ldsm4(kbf[0], Ku + (uint32_t)(krow0 * SSTRIDE) * 2 + koffK);

        #pragma unroll
        for (int idx = 0; idx < 16; idx++) {
            const int ks = idx >> 2, p = idx & 3;
            const int cb = idx & 1;
            if (idx + 1 < 16) {
                const int ksn = (idx + 1) >> 2, pn = (idx + 1) & 3;
                ldsm4(kbf[cb ^ 1], Ku + (uint32_t)((krow0 + pn * 16) * SSTRIDE + ksn * 16) * 2 + koffK);
            }
            if (p == 1 && ks < 3)
                ldsm4(qaf[(ks + 1) & 1], Qu + qoff + (uint32_t)((ks + 1) * 16) * 2);
            mma16816(sacc[2 * p],     qaf[ks & 1], kbf[cb][0], kbf[cb][1]);
            mma16816(sacc[2 * p + 1], qaf[ks & 1], kbf[cb][2], kbf[cb][3]);
        }

        float mxA = -1e30f, mxB = -1e30f;
        #pragma unroll
        for (int nt = 0; nt < 8; nt++) {
            mxA = fmaxf(mxA, fmaxf(sacc[nt][0], sacc[nt][1]));
            mxB = fmaxf(mxB, fmaxf(sacc[nt][2], sacc[nt][3]));
        }
        mxA = fmaxf(mxA, __shfl_xor_sync(0xffffffffu, mxA, 1));
        mxA = fmaxf(mxA, __shfl_xor_sync(0xffffffffu, mxA, 2));
        mxB = fmaxf(mxB, __shfl_xor_sync(0xffffffffu, mxB, 1));
        mxB = fmaxf(mxB, __shfl_xor_sync(0xffffffffu, mxB, 2));
        float nmA = fmaxf(mA, mxA), nmB = fmaxf(mB, mxB);
        float scA = __expf(mA - nmA), scB = __expf(mB - nmB);
        mA = nmA; mB = nmB;
        float rsA = 0.0f, rsB = 0.0f;
        #pragma unroll
        for (int nt = 0; nt < 8; nt++) {
            sacc[nt][0] = __expf(sacc[nt][0] - nmA);
            sacc[nt][1] = __expf(sacc[nt][1] - nmA);
            sacc[nt][2] = __expf(sacc[nt][2] - nmB);
            sacc[nt][3] = __expf(sacc[nt][3] - nmB);
            rsA += sacc[nt][0] + sacc[nt][1];
            rsB += sacc[nt][2] + sacc[nt][3];
        }
        rsA += __shfl_xor_sync(0xffffffffu, rsA, 1);
        rsA += __shfl_xor_sync(0xffffffffu, rsA, 2);
        rsB += __shfl_xor_sync(0xffffffffu, rsB, 1);
        rsB += __shfl_xor_sync(0xffffffffu, rsB, 2);
        lA = lA * scA + rsA;
        lB = lB * scB + rsB;
        #pragma unroll
        for (int dt = 0; dt < 8; dt++) {
            accO[dt][0] *= scA; accO[dt][1] *= scA;
            accO[dt][2] *= scB; accO[dt][3] *= scB;
        }

        uint32_t vbf[2][4];
        uint32_t pf[4];
        ldsm4t(vbf[0], Vu + (uint32_t)(vrow0 * SSTRIDE) * 2 + vcol0);
        #pragma unroll
        for (int idx = 0; idx < 16; idx++) {
            const int ks = idx >> 2, p = idx & 3;
            const int cb = idx & 1;
            if (p == 0) {
                pf[0] = h2u(sacc[2 * ks][0],     sacc[2 * ks][1]);
                pf[1] = h2u(sacc[2 * ks][2],     sacc[2 * ks][3]);
                pf[2] = h2u(sacc[2 * ks + 1][0], sacc[2 * ks + 1][1]);
                pf[3] = h2u(sacc[2 * ks + 1][2], sacc[2 * ks + 1][3]);
            }
            if (idx + 1 < 16) {
                const int ksn = (idx + 1) >> 2, pn = (idx + 1) & 3;
                ldsm4t(vbf[cb ^ 1], Vu + (uint32_t)((vrow0 + ksn * 16) * SSTRIDE + pn * 16) * 2 + vcol0);
            }
            mma16816(accO[2 * p],     pf, vbf[cb][0], vbf[cb][1]);
            mma16816(accO[2 * p + 1], pf, vbf[cb][2], vbf[cb][3]);
        }
    }

    float invA = 1.0f / lA, invB = 1.0f / lB;
    const int b_ = bh >> 4, h_ = bh & 15;
    const int rowA = qt * 128 + mrow + (lane >> 2);
    #pragma unroll
    for (int dt = 0; dt < 8; dt++) {
        int d = dt * 8 + ((lane & 3) << 1);
        __half* o0 = &g_attnh[((size_t)(b_ * S_LEN + rowA)) * EMB + h_ * HD + d];
        *(__half2*)o0 = __floats2half2_rn(accO[dt][0] * invA, accO[dt][1] * invA);
        __half* o1 = &g_attnh[((size_t)(b_ * S_LEN + rowA + 8)) * EMB + h_ * HD + d];
        *(__half2*)o1 = __floats2half2_rn(accO[dt][2] * invB, accO[dt][3] * invB);
    }
}

extern "C" void kernel_launch(void* const* d_in, const int* in_sizes, int n_in,
                              void* d_out, int out_size)
{
    const float* x  = (const float*)d_in[0];
    const float* wq = (const float*)d_in[1];
    const float* bq = (const float*)d_in[2];
    const float* wk = (const float*)d_in[3];
    const float* bk = (const float*)d_in[4];
    const float* wv = (const float*)d_in[5];
    const float* bv = (const float*)d_in[6];
    const float* wo = (const float*)d_in[7];
    const float* bo = (const float*)d_in[8];
    float* out = (float*)d_out;

    const int gemm_smem  = 3 * STG_G2;               // 82944 B -> 2 CTAs/SM
    const int flash_smem = TILE_Q + 3 * STG_KV;      // 73728 B
    static int attr_set = 0;
    if (!attr_set) {
        cudaFuncSetAttribute(qkv_gemm_kernel, cudaFuncAttributeMaxDynamicSharedMemorySize, gemm_smem);
        cudaFuncSetAttribute(out_gemm_kernel, cudaFuncAttributeMaxDynamicSharedMemorySize, gemm_smem);
        cudaFuncSetAttribute(flash_kernel,    cudaFuncAttributeMaxDynamicSharedMemorySize, flash_smem);
        attr_set = 1;
    }

    cvt_kernel<<<4096, 256>>>(x, wq, wk, wv, wo);

    dim3 gq(EMB / 128, MTOT / 64, 3);    // 8 x 64 x 3
    qkv_gemm_kernel<<<gq, 256, gemm_smem>>>(bq, bk, bv);

    flash_kernel<<<dim3(S_LEN / 128, BATCH * NH), 256, flash_smem>>>();

    dim3 gg(EMB / 128, MTOT / 64);       // 8 x 64
    out_gemm_kernel<<<gg, 256, gemm_smem>>>(bo, out);
}

// round 15
// speedup vs baseline: 1.1329x; 1.1329x over previous
#include <cuda_runtime.h>
#include <cuda_fp16.h>
#include <cstdint>

#define S_LEN 2048
#define EMB   1024
#define NH    16
#define HD    64
#define BATCH 2
#define MTOT  (BATCH*S_LEN)   // 4096

// Scratch (device globals: allocation-free). Q/K/V fp16 (Q pre-scaled), attn fp16.
__device__ __half g_q[BATCH*NH*S_LEN*HD];
__device__ __half g_k[BATCH*NH*S_LEN*HD];
__device__ __half g_v[BATCH*NH*S_LEN*HD];
__device__ __half g_attnh[MTOT*EMB];

#define SSTRIDE 72     // flash smem row stride in halves (144 B)
#define GSTRIDE 136    // gemm smem row stride in halves (272 B), K-chunk 128
#define GTILE   (128*GSTRIDE)          // halves per gemm tile
#define GEMM_SMEM (2*GTILE*2)          // 69632 B (A + B), dynamic

// ---------------------------------------------------------------------------
// helpers
// ---------------------------------------------------------------------------
__device__ __forceinline__ uint32_t smem_u32(const void* p) {
    uint32_t a;
    asm("{ .reg .u64 t; cvta.to.shared.u64 t, %1; cvt.u32.u64 %0, t; }" : "=r"(a) : "l"(p));
    return a;
}
__device__ __forceinline__ uint32_t h2u(float a, float b) {
    __half2 h = __floats2half2_rn(a, b);
    return *(uint32_t*)&h;
}
__device__ __forceinline__ void ldsm4(uint32_t* r, uint32_t a) {
    asm volatile("ldmatrix.sync.aligned.m8n8.x4.shared.b16 {%0,%1,%2,%3}, [%4];"
        : "=r"(r[0]), "=r"(r[1]), "=r"(r[2]), "=r"(r[3]) : "r"(a));
}
__device__ __forceinline__ void ldsm4t(uint32_t* r, uint32_t a) {
    asm volatile("ldmatrix.sync.aligned.m8n8.x4.trans.shared.b16 {%0,%1,%2,%3}, [%4];"
        : "=r"(r[0]), "=r"(r[1]), "=r"(r[2]), "=r"(r[3]) : "r"(a));
}
__device__ __forceinline__ void mma16816(float* d, const uint32_t* a, uint32_t b0, uint32_t b1) {
    asm volatile(
        "mma.sync.aligned.m16n8k16.row.col.f32.f16.f16.f32 "
        "{%0,%1,%2,%3}, {%4,%5,%6,%7}, {%8,%9}, {%0,%1,%2,%3};"
        : "+f"(d[0]), "+f"(d[1]), "+f"(d[2]), "+f"(d[3])
        : "r"(a[0]), "r"(a[1]), "r"(a[2]), "r"(a[3]), "r"(b0), "r"(b1));
}

// ---------------------------------------------------------------------------
// HGEMM (R4 structure, K-chunk widened 64 -> 128: half the barriers and half
// the exposed-load episodes). C = A @ W^T + bias; A,W fp32 row-major,
// converted to fp16 inline while staging smem. CTA 128x128, 8 warps (4m x 2n),
// 69.6 KB dynamic smem -> 2 CTAs/SM.
// MODE 0: fp32 C.  MODE 1: fp16 scatter to [B,H,S,D] with scale.
// ---------------------------------------------------------------------------
template <int MODE>
__device__ __forceinline__
void hgemm_body(const float* __restrict__ A, const float* __restrict__ W,
                const float* __restrict__ bias, void* __restrict__ Cout, float oscale)
{
    extern __shared__ __half gsm[];
    __half* sA = gsm;
    __half* sB = gsm + GTILE;

    const int tid = threadIdx.x;
    const int wid = tid >> 5, lane = tid & 31;
    const int wm = wid >> 1, wn = wid & 1;
    const int m0 = blockIdx.y * 128, n0 = blockIdx.x * 128;

    float acc[2][8][4];
    #pragma unroll
    for (int mt = 0; mt < 2; mt++)
        #pragma unroll
        for (int nt = 0; nt < 8; nt++)
            #pragma unroll
            for (int r = 0; r < 4; r++) acc[mt][nt][r] = 0.0f;

    const float* Ag = A + (size_t)m0 * EMB;
    const float* Bg = W + (size_t)n0 * EMB;
    const uint32_t sAu = smem_u32(sA), sBu = smem_u32(sB);

    for (int kc = 0; kc < EMB; kc += 128) {
        __syncthreads();
        // stage A[128x128] and B[128x128] fp32 -> fp16 (16 units of 4 floats each per thread per tile)
        #pragma unroll
        for (int i = 0; i < 16; i++) {
            int g = tid + 256 * i;              // 0..4095
            int row = g >> 5, u = g & 31;
            float4 f = *(const float4*)(Ag + (size_t)row * EMB + kc + u * 4);
            *(uint2*)&sA[row * GSTRIDE + u * 4] = make_uint2(h2u(f.x, f.y), h2u(f.z, f.w));
        }
        #pragma unroll
        for (int i = 0; i < 16; i++) {
            int g = tid + 256 * i;
            int row = g >> 5, u = g & 31;
            float4 f = *(const float4*)(Bg + (size_t)row * EMB + kc + u * 4);
            *(uint2*)&sB[row * GSTRIDE + u * 4] = make_uint2(h2u(f.x, f.y), h2u(f.z, f.w));
        }
        __syncthreads();

        #pragma unroll
        for (int ks = 0; ks < 8; ks++) {
            uint32_t af[2][4];
            #pragma unroll
            for (int mt = 0; mt < 2; mt++) {
                int row = wm * 32 + mt * 16 + (lane & 15);
                ldsm4(af[mt], sAu + (uint32_t)(row * GSTRIDE + ks * 16 + ((lane >> 4) << 3)) * 2);
            }
            #pragma unroll
            for (int p = 0; p < 4; p++) {
                uint32_t bf[4];
                int row = wn * 64 + p * 16 + ((lane >> 4) << 3) + (lane & 7);
                int koff = ks * 16 + (((lane >> 3) & 1) << 3);
                ldsm4(bf, sBu + (uint32_t)(row * GSTRIDE + koff) * 2);
                #pragma unroll
                for (int mt = 0; mt < 2; mt++) {
                    mma16816(acc[mt][2 * p],     af[mt], bf[0], bf[1]);
                    mma16816(acc[mt][2 * p + 1], af[mt], bf[2], bf[3]);
                }
            }
        }
    }

    // epilogue
    #pragma unroll
    for (int mt = 0; mt < 2; mt++) {
        int rA = m0 + wm * 32 + mt * 16 + (lane >> 2);
        #pragma unroll
        for (int nt = 0; nt < 8; nt++) {
            int n = n0 + wn * 64 + nt * 8 + ((lane & 3) << 1);
            float b0 = bias[n], b1 = bias[n + 1];
            float v00 = acc[mt][nt][0] + b0, v01 = acc[mt][nt][1] + b1;
            float v10 = acc[mt][nt][2] + b0, v11 = acc[mt][nt][3] + b1;
            if (MODE == 0) {
                float* C = (float*)Cout;
                C[(size_t)rA * EMB + n]           = v00;
                C[(size_t)rA * EMB + n + 1]       = v01;
                C[(size_t)(rA + 8) * EMB + n]     = v10;
                C[(size_t)(rA + 8) * EMB + n + 1] = v11;
            } else {
                __half* C = (__half*)Cout;
                int h_ = n >> 6, d_ = n & 63;
                {
                    int b_ = rA >> 11, s_ = rA & 2047;
                    size_t base = (((size_t)(b_ * NH + h_) * S_LEN) + s_) * HD + d_;
                    *(__half2*)&C[base] = __floats2half2_rn(v00 * oscale, v01 * oscale);
                }
                {
                    int r2 = rA + 8;
                    int b_ = r2 >> 11, s_ = r2 & 2047;
                    size_t base = (((size_t)(b_ * NH + h_) * S_LEN) + s_) * HD + d_;
                    *(__half2*)&C[base] = __floats2half2_rn(v10 * oscale, v11 * oscale);
                }
            }
        }
    }
}

__global__ __launch_bounds__(256, 2)
void qkv_gemm_kernel(const float* __restrict__ x,
                     const float* __restrict__ wq, const float* __restrict__ bq,
                     const float* __restrict__ wk, const float* __restrict__ bk,
                     const float* __restrict__ wv, const float* __restrict__ bv)
{
    if (blockIdx.z == 0)      hgemm_body<1>(x, wq, bq, g_q, 0.125f);
    else if (blockIdx.z == 1) hgemm_body<1>(x, wk, bk, g_k, 1.0f);
    else                      hgemm_body<1>(x, wv, bv, g_v, 1.0f);
}

__global__ __launch_bounds__(256, 2)
void out_gemm_kernel(const float* __restrict__ wo, const float* __restrict__ bo,
                     float* __restrict__ out)
{
    // A operand is fp16 attn output; widen to the fp32 loader path via a
    // dedicated staging loop below is unnecessary: reuse hgemm by converting
    // through a thin wrapper is impossible, so out_gemm stages fp16 directly.
    extern __shared__ __half gsm[];
    __half* sA = gsm;
    __half* sB = gsm + GTILE;

    const int tid = threadIdx.x;
    const int wid = tid >> 5, lane = tid & 31;
    const int wm = wid >> 1, wn = wid & 1;
    const int m0 = blockIdx.y * 128, n0 = blockIdx.x * 128;

    float acc[2][8][4];
    #pragma unroll
    for (int mt = 0; mt < 2; mt++)
        #pragma unroll
        for (int nt = 0; nt < 8; nt++)
            #pragma unroll
            for (int r = 0; r < 4; r++) acc[mt][nt][r] = 0.0f;

    const __half* Ag = g_attnh + (size_t)m0 * EMB;
    const float*  Bg = wo + (size_t)n0 * EMB;
    const uint32_t sAu = smem_u32(sA), sBu = smem_u32(sB);

    for (int kc = 0; kc < EMB; kc += 128) {
        __syncthreads();
        // A fp16: 128x128 halves = 2048 uint4 units -> 8 per thread
        #pragma unroll
        for (int i = 0; i < 8; i++) {
            int g = tid + 256 * i;              // 0..2047
            int row = g >> 4, u = g & 15;       // u: 16B unit (8 halves)
            *(uint4*)&sA[row * GSTRIDE + u * 8] =
                *(const uint4*)(Ag + (size_t)row * EMB + kc + u * 8);
        }
        // B fp32 -> fp16
        #pragma unroll
        for (int i = 0; i < 16; i++) {
            int g = tid + 256 * i;
            int row = g >> 5, u = g & 31;
            float4 f = *(const float4*)(Bg + (size_t)row * EMB + kc + u * 4);
            *(uint2*)&sB[row * GSTRIDE + u * 4] = make_uint2(h2u(f.x, f.y), h2u(f.z, f.w));
        }
        __syncthreads();

        #pragma unroll
        for (int ks = 0; ks < 8; ks++) {
            uint32_t af[2][4];
            #pragma unroll
            for (int mt = 0; mt < 2; mt++) {
                int row = wm * 32 + mt * 16 + (lane & 15);
                ldsm4(af[mt], sAu + (uint32_t)(row * GSTRIDE + ks * 16 + ((lane >> 4) << 3)) * 2);
            }
            #pragma unroll
            for (int p = 0; p < 4; p++) {
                uint32_t bf[4];
                int row = wn * 64 + p * 16 + ((lane >> 4) << 3) + (lane & 7);
                int koff = ks * 16 + (((lane >> 3) & 1) << 3);
                ldsm4(bf, sBu + (uint32_t)(row * GSTRIDE + koff) * 2);
                #pragma unroll
                for (int mt = 0; mt < 2; mt++) {
                    mma16816(acc[mt][2 * p],     af[mt], bf[0], bf[1]);
                    mma16816(acc[mt][2 * p + 1], af[mt], bf[2], bf[3]);
                }
            }
        }
    }

    #pragma unroll
    for (int mt = 0; mt < 2; mt++) {
        int rA = m0 + wm * 32 + mt * 16 + (lane >> 2);
        #pragma unroll
        for (int nt = 0; nt < 8; nt++) {
            int n = n0 + wn * 64 + nt * 8 + ((lane & 3) << 1);
            out[(size_t)rA * EMB + n]           = acc[mt][nt][0] + bo[n];
            out[(size_t)rA * EMB + n + 1]       = acc[mt][nt][1] + bo[n + 1];
            out[(size_t)(rA + 8) * EMB + n]     = acc[mt][nt][2] + bo[n];
            out[(size_t)(rA + 8) * EMB + n + 1] = acc[mt][nt][3] + bo[n + 1];
        }
    }
}

// ---------------------------------------------------------------------------
// Flash attention — exact R4 structure (plain loads, static smem, 2 barriers
// per 64-tile). CTA: 128 Q rows, 8 warps x 16 rows, Bc=64.
// ---------------------------------------------------------------------------
__global__ __launch_bounds__(256)
void flash_kernel()
{
    __shared__ __half Qs[128 * SSTRIDE];
    __shared__ __half Ks[64 * SSTRIDE];
    __shared__ __half Vs[64 * SSTRIDE];

    const int tid = threadIdx.x, wid = tid >> 5, lane = tid & 31;
    const int qt = blockIdx.x;
    const int bh = blockIdx.y;

    const __half* Qg = g_q + ((size_t)bh * S_LEN + qt * 128) * HD;
    const __half* Kg = g_k + (size_t)bh * S_LEN * HD;
    const __half* Vg = g_v + (size_t)bh * S_LEN * HD;

    #pragma unroll
    for (int i = 0; i < 4; i++) {
        int g = tid + 256 * i;
        int row = g >> 3, u = g & 7;
        *(uint4*)&Qs[row * SSTRIDE + u * 8] = *(const uint4*)(Qg + (size_t)row * HD + u * 8);
    }

    float accO[8][4];
    #pragma unroll
    for (int dt = 0; dt < 8; dt++)
        #pragma unroll
        for (int r = 0; r < 4; r++) accO[dt][r] = 0.0f;
    float mA = -1e30f, mB = -1e30f, lA = 0.0f, lB = 0.0f;

    const int mrow = wid * 16;
    const uint32_t Qu = smem_u32(Qs), Ku = smem_u32(Ks), Vu = smem_u32(Vs);

    for (int kt = 0; kt < S_LEN / 64; kt++) {
        __syncthreads();
        const __half* Kp = Kg + (size_t)kt * 64 * HD;
        const __half* Vp = Vg + (size_t)kt * 64 * HD;
        #pragma unroll
        for (int i = 0; i < 2; i++) {
            int g = tid + 256 * i;
            int row = g >> 3, u = g & 7;
            *(uint4*)&Ks[row * SSTRIDE + u * 8] = *(const uint4*)(Kp + (size_t)row * HD + u * 8);
            *(uint4*)&Vs[row * SSTRIDE + u * 8] = *(const uint4*)(Vp + (size_t)row * HD + u * 8);
        }
        __syncthreads();

        // S = Q @ K^T  (Q carries 1/8)
        float sacc[8][4];
        #pragma unroll
        for (int nt = 0; nt < 8; nt++)
            #pragma unroll
            for (int r = 0; r < 4; r++) sacc[nt][r] = 0.0f;
        #pragma unroll
        for (int ks = 0; ks < 4; ks++) {
            uint32_t af[4];
            ldsm4(af, Qu + (uint32_t)((mrow + (lane & 15)) * SSTRIDE + ks * 16 + ((lane >> 4) << 3)) * 2);
            #pragma unroll
            for (int p = 0; p < 4; p++) {
                uint32_t bf[4];
                int row = p * 16 + ((lane >> 4) << 3) + (lane & 7);
                int koff = ks * 16 + (((lane >> 3) & 1) << 3);
                ldsm4(bf, Ku + (uint32_t)(row * SSTRIDE + koff) * 2);
                mma16816(sacc[2 * p],     af, bf[0], bf[1]);
                mma16816(sacc[2 * p + 1], af, bf[2], bf[3]);
            }
        }

        // online softmax
        float mxA = -1e30f, mxB = -1e30f;
        #pragma unroll
        for (int nt = 0; nt < 8; nt++) {
            mxA = fmaxf(mxA, fmaxf(sacc[nt][0], sacc[nt][1]));
            mxB = fmaxf(mxB, fmaxf(sacc[nt][2], sacc[nt][3]));
        }
        mxA = fmaxf(mxA, __shfl_xor_sync(0xffffffffu, mxA, 1));
        mxA = fmaxf(mxA, __shfl_xor_sync(0xffffffffu, mxA, 2));
        mxB = fmaxf(mxB, __shfl_xor_sync(0xffffffffu, mxB, 1));
        mxB = fmaxf(mxB, __shfl_xor_sync(0xffffffffu, mxB, 2));
        float nmA = fmaxf(mA, mxA), nmB = fmaxf(mB, mxB);
        float scA = __expf(mA - nmA), scB = __expf(mB - nmB);
        mA = nmA; mB = nmB;
        float rsA = 0.0f, rsB = 0.0f;
        #pragma unroll
        for (int nt = 0; nt < 8; nt++) {
            sacc[nt][0] = __expf(sacc[nt][0] - nmA);
            sacc[nt][1] = __expf(sacc[nt][1] - nmA);
            sacc[nt][2] = __expf(sacc[nt][2] - nmB);
            sacc[nt][3] = __expf(sacc[nt][3] - nmB);
            rsA += sacc[nt][0] + sacc[nt][1];
            rsB += sacc[nt][2] + sacc[nt][3];
        }
        rsA += __shfl_xor_sync(0xffffffffu, rsA, 1);
        rsA += __shfl_xor_sync(0xffffffffu, rsA, 2);
        rsB += __shfl_xor_sync(0xffffffffu, rsB, 1);
        rsB += __shfl_xor_sync(0xffffffffu, rsB, 2);
        lA = lA * scA + rsA;
        lB = lB * scB + rsB;
        #pragma unroll
        for (int dt = 0; dt < 8; dt++) {
            accO[dt][0] *= scA; accO[dt][1] *= scA;
            accO[dt][2] *= scB; accO[dt][3] *= scB;
        }

        // O += P @ V
        #pragma unroll
        for (int ks = 0; ks < 4; ks++) {
            uint32_t pf[4];
            pf[0] = h2u(sacc[2 * ks][0],     sacc[2 * ks][1]);
            pf[1] = h2u(sacc[2 * ks][2],     sacc[2 * ks][3]);
            pf[2] = h2u(sacc[2 * ks + 1][0], sacc[2 * ks + 1][1]);
            pf[3] = h2u(sacc[2 * ks + 1][2], sacc[2 * ks + 1][3]);
            #pragma unroll
            for (int p = 0; p < 4; p++) {
                uint32_t bf[4];
                int row = ks * 16 + (((lane >> 3) & 1) << 3) + (lane & 7);
                int col = p * 16 + ((lane >> 4) << 3);
                ldsm4t(bf, Vu + (uint32_t)(row * SSTRIDE + col) * 2);
                mma16816(accO[2 * p],     pf, bf[0], bf[1]);
                mma16816(accO[2 * p + 1], pf, bf[2], bf[3]);
            }
        }
    }

    // normalize + write [B,S,E] fp16
    float invA = 1.0f / lA, invB = 1.0f / lB;
    const int b_ = bh >> 4, h_ = bh & 15;
    const int rowA = qt * 128 + mrow + (lane >> 2);
    #pragma unroll
    for (int dt = 0; dt < 8; dt++) {
        int d = dt * 8 + ((lane & 3) << 1);
        __half* o0 = &g_attnh[((size_t)(b_ * S_LEN + rowA)) * EMB + h_ * HD + d];
        *(__half2*)o0 = __floats2half2_rn(accO[dt][0] * invA, accO[dt][1] * invA);
        __half* o1 = &g_attnh[((size_t)(b_ * S_LEN + rowA + 8)) * EMB + h_ * HD + d];
        *(__half2*)o1 = __floats2half2_rn(accO[dt][2] * invB, accO[dt][3] * invB);
    }
}

extern "C" void kernel_launch(void* const* d_in, const int* in_sizes, int n_in,
                              void* d_out, int out_size)
{
    const float* x  = (const float*)d_in[0];
    const float* wq = (const float*)d_in[1];
    const float* bq = (const float*)d_in[2];
    const float* wk = (const float*)d_in[3];
    const float* bk = (const float*)d_in[4];
    const float* wv = (const float*)d_in[5];
    const float* bv = (const float*)d_in[6];
    const float* wo = (const float*)d_in[7];
    const float* bo = (const float*)d_in[8];
    float* out = (float*)d_out;

    static int attr_set = 0;
    if (!attr_set) {
        cudaFuncSetAttribute(qkv_gemm_kernel, cudaFuncAttributeMaxDynamicSharedMemorySize, GEMM_SMEM);
        cudaFuncSetAttribute(out_gemm_kernel, cudaFuncAttributeMaxDynamicSharedMemorySize, GEMM_SMEM);
        attr_set = 1;
    }

    dim3 gq(EMB / 128, MTOT / 128, 3);   // 8 x 32 x 3
    qkv_gemm_kernel<<<gq, 256, GEMM_SMEM>>>(x, wq, bq, wk, bk, wv, bv);

    flash_kernel<<<dim3(S_LEN / 128, BATCH * NH), 256>>>();   // 16 x 32

    dim3 gg(EMB / 128, MTOT / 128);      // 8 x 32
    out_gemm_kernel<<<gg, 256, GEMM_SMEM>>>(wo, bo, out);
}